// round 12
// baseline (speedup 1.0000x reference)
#include <cuda_runtime.h>

// Random_RNN two-hop — algebraic collapse, 2-kernel pipeline.
//   out = (W2*W1) * x^T, M = W2*W1 is 256x256 dense.
// k_build: one scan, buckets (hop1 keyed by assoc j, hop2 keyed by OUTPUT o),
//          line-padded counters (L2 atomic units serialize per 128B line).
// k_fuse:  block o folds its in-edges (j,w2) x j's in-edges (s,w1) into a
//          SMEM Mrow via smem atomics, then GEMMs the row against xT.
//          M never exists in global memory; one launch gap removed.
// Replay determinism: c2[o] consumed-and-reset by its only reader; c1 reset
// by the LAST finishing block (g_done completion counter, restored to 0).

#define B      128
#define IN_F   256
#define N_ASS  4096
#define OUT_F  256
#define ASS0   256
#define OUT0   (IN_F + N_ASS)   // 4352
#define CAP1   40               // assoc in-degree: E 12.8, sd 3.5 (max ~26)
#define CAP2   288              // output in-degree: E 204.8, sd 14 (max ~252)
#define XT_N   (IN_F * B)       // 32768
#define CSTR   32               // counter stride: 32 ints = 128B = 1 L2 line

__device__ float2 g_b1[N_ASS * CAP1];   // in-edges of j:  {s (int bits), w1}
__device__ float2 g_b2[OUT_F * CAP2];   // in-edges of o:  {j (int bits), w2}
__device__ int    g_c1[N_ASS * CSTR];   // one counter per L2 line
__device__ int    g_c2[OUT_F * CSTR];
__device__ float  g_xT[IN_F * B];       // x transposed [s][b]
__device__ int    g_done;               // k_fuse completion counter (ret. to 0)

// ---------------------------------------------------------------- k1: build
// Proven scan shape: 1184x256 grid-stride, int4 dst scan, conditional
// vectorized side loads, line-private counter atomics.
__global__ void __launch_bounds__(256, 8)
k_build(const float* __restrict__ x,
        const int* __restrict__ in_src, const int* __restrict__ in_dst,
        const float* __restrict__ in_w, int E_in,
        const int* __restrict__ a_src, const int* __restrict__ a_dst,
        const float* __restrict__ a_w, int E_ass) {
    const int i  = blockIdx.x * 256 + threadIdx.x;
    const int nt = gridDim.x * 256;

    // x [B][IN_F] -> xT [IN_F][B]
    for (int idx = i; idx < XT_N; idx += nt) {
        int b = idx >> 8, s = idx & 255;               // IN_F == 256
        g_xT[s * B + b] = x[idx];
    }

    // hop1 edges (~52K): bucket by dst assoc j
    for (int e = i; e < E_in; e += nt) {
        int   j = in_dst[e] - ASS0;
        int   s = in_src[e];
        float w = in_w[e];
        int pos = atomicAdd(&g_c1[j * CSTR], 1);
        g_b1[j * CAP1 + pos] = make_float2(__int_as_float(s), w);
    }

    // hop2 edges (~891K): int4 dst scan, filter dst >= OUT0; bucket by dst o
    const int     E4  = E_ass >> 2;
    const int4*   a4  = (const int4*)a_dst;
    const int4*   s4p = (const int4*)a_src;
    const float4* w4p = (const float4*)a_w;
    for (int q = i; q < E4; q += nt) {
        int4 d4 = __ldg(&a4[q]);
        if (d4.x >= OUT0 || d4.y >= OUT0 || d4.z >= OUT0 || d4.w >= OUT0) {
            int4   s4 = __ldg(&s4p[q]);
            float4 w4 = __ldg(&w4p[q]);
            int   dd[4] = {d4.x, d4.y, d4.z, d4.w};
            int   ss[4] = {s4.x, s4.y, s4.z, s4.w};
            float ww[4] = {w4.x, w4.y, w4.z, w4.w};
#pragma unroll
            for (int m = 0; m < 4; m++) {
                if (dd[m] >= OUT0) {
                    int o   = dd[m] - OUT0;
                    int j   = ss[m] - ASS0;
                    int pos = atomicAdd(&g_c2[o * CSTR], 1);
                    g_b2[o * CAP2 + pos] =
                        make_float2(__int_as_float(j), ww[m]);
                }
            }
        }
    }
    for (int e = (E4 << 2) + i; e < E_ass; e += nt) {  // tail (E_ass % 4)
        int d = a_dst[e];
        if (d >= OUT0) {
            int   o = d - OUT0;
            int   j = a_src[e] - ASS0;
            float w = a_w[e];
            int pos = atomicAdd(&g_c2[o * CSTR], 1);
            g_b2[o * CAP2 + pos] = make_float2(__int_as_float(j), w);
        }
    }
}

// ---------------------------------------------------------------- k2: fuse
// Block o: fold M row o in SMEM, then GEMM it against xT.
__global__ void __launch_bounds__(512) k_fuse(float* __restrict__ out) {
    __shared__ float sM[IN_F];               // M[o][*]
    __shared__ float part[3][B];
    __shared__ int   sc, slast;
    const int o   = blockIdx.x;
    const int tid = threadIdx.x;

    for (int s = tid; s < IN_F; s += 512) sM[s] = 0.f;
    if (tid == 0) { sc = g_c2[o * CSTR]; g_c2[o * CSTR] = 0; }  // sole reader
    __syncthreads();

    // ---- fold: edge t of o (n2 <= ~252 < 512), cross with j's in-edges ----
    int n2 = sc;
    if (tid < n2) {
        float2 p2 = __ldg(&g_b2[o * CAP2 + tid]);
        int   j  = __float_as_int(p2.x);
        float w2 = p2.y;
        int   n1 = __ldg(&g_c1[j * CSTR]);            // read-only here
        const float2* e1 = &g_b1[j * CAP1];
        for (int k = 0; k < n1; k++) {                // n1 <= ~26
            float2 p1 = __ldg(&e1[k]);
            atomicAdd(&sM[__float_as_int(p1.x)], p1.y * w2);
        }
    }
    __syncthreads();

    // ---- gemm: out[b][o] = sum_s sM[s] * xT[s][b] ----
    int g = tid >> 7, b = tid & 127;
    float r = 0.f;
    int s0 = g * 64;
#pragma unroll
    for (int sr = 0; sr < 64; sr += 8) {              // 8 independent loads
        float v[8];
#pragma unroll
        for (int k = 0; k < 8; k++)
            v[k] = g_xT[(s0 + sr + k) * B + b];
#pragma unroll
        for (int k = 0; k < 8; k++)
            r += sM[s0 + sr + k] * v[k];
    }
    if (g > 0) part[g - 1][b] = r;
    __syncthreads();
    if (g == 0)
        out[b * OUT_F + o] = r + part[0][b] + part[1][b] + part[2][b];

    // ---- last block out resets g_c1 (all blocks done reading it) ----
    __syncthreads();
    if (tid == 0) slast = (atomicAdd(&g_done, 1) == OUT_F - 1) ? 1 : 0;
    __syncthreads();
    if (slast) {
        for (int j = tid; j < N_ASS; j += 512) g_c1[j * CSTR] = 0;
        if (tid == 0) g_done = 0;                     // restore for replay
    }
}

// ---------------------------------------------------------------- launch
extern "C" void kernel_launch(void* const* d_in, const int* in_sizes, int n_in,
                              void* d_out, int out_size) {
    const float* x      = (const float*)d_in[0];
    const float* in_w   = (const float*)d_in[1];
    const float* a_w    = (const float*)d_in[2];
    const int*   in_src = (const int*)d_in[3];
    const int*   in_dst = (const int*)d_in[4];
    const int*   a_src  = (const int*)d_in[5];
    const int*   a_dst  = (const int*)d_in[6];
    int E_in  = in_sizes[1];
    int E_ass = in_sizes[2];
    float* out = (float*)d_out;

    k_build<<<1184, 256>>>(x, in_src, in_dst, in_w, E_in,
                           a_src, a_dst, a_w, E_ass);
    k_fuse <<<OUT_F, 512>>>(out);
}

// round 13
// speedup vs baseline: 1.0098x; 1.0098x over previous
#include <cuda_runtime.h>

// Random_RNN two-hop — algebraic collapse, 2-kernel pipeline, parallel fold.
//   out = (W2*W1) * x^T ; row o of M folded in SMEM, GEMMed immediately.
//
// R12 lesson: per-thread serial fold chains (15 dependent L2 trips) cost 18us.
// This round: fold restructured as (a) parallel stage of all edge records and
// all n1 counts (2 latency rounds total), (b) warp-per-edge cross with 2-edge
// interleave (~7 rounds). Build kernel unchanged (proven).
//
// Invariants: line-padded counters (L2 atomics serialize per 128B line),
// counters consumed-and-reset (c2 by sole reader; c1 by last-block-out with
// g_done restored) -> graph replays see identical state.

#define B      128
#define IN_F   256
#define N_ASS  4096
#define OUT_F  256
#define ASS0   256
#define OUT0   (IN_F + N_ASS)   // 4352
#define CAP1   40               // assoc in-degree: E 12.8, sd 3.5 (max ~26)
#define CAP2   288              // output in-degree: E 204.8, sd 14 (max ~252)
#define XT_N   (IN_F * B)       // 32768
#define CSTR   32               // counter stride: 32 ints = 128B = 1 L2 line

__device__ float2 g_b1[N_ASS * CAP1];   // in-edges of j:  {s (int bits), w1}
__device__ float2 g_b2[OUT_F * CAP2];   // in-edges of o:  {j (int bits), w2}
__device__ int    g_c1[N_ASS * CSTR];   // one counter per L2 line
__device__ int    g_c2[OUT_F * CSTR];
__device__ float  g_xT[IN_F * B];       // x transposed [s][b]
__device__ int    g_done;               // k_fuse completion counter (ret. to 0)

// ---------------------------------------------------------------- k1: build
__global__ void __launch_bounds__(256, 8)
k_build(const float* __restrict__ x,
        const int* __restrict__ in_src, const int* __restrict__ in_dst,
        const float* __restrict__ in_w, int E_in,
        const int* __restrict__ a_src, const int* __restrict__ a_dst,
        const float* __restrict__ a_w, int E_ass) {
    const int i  = blockIdx.x * 256 + threadIdx.x;
    const int nt = gridDim.x * 256;

    // x [B][IN_F] -> xT [IN_F][B]
    for (int idx = i; idx < XT_N; idx += nt) {
        int b = idx >> 8, s = idx & 255;               // IN_F == 256
        g_xT[s * B + b] = x[idx];
    }

    // hop1 edges (~52K): bucket by dst assoc j
    for (int e = i; e < E_in; e += nt) {
        int   j = in_dst[e] - ASS0;
        int   s = in_src[e];
        float w = in_w[e];
        int pos = atomicAdd(&g_c1[j * CSTR], 1);
        g_b1[j * CAP1 + pos] = make_float2(__int_as_float(s), w);
    }

    // hop2 edges (~891K): int4 dst scan, filter dst >= OUT0; bucket by dst o
    const int     E4  = E_ass >> 2;
    const int4*   a4  = (const int4*)a_dst;
    const int4*   s4p = (const int4*)a_src;
    const float4* w4p = (const float4*)a_w;
    for (int q = i; q < E4; q += nt) {
        int4 d4 = __ldg(&a4[q]);
        if (d4.x >= OUT0 || d4.y >= OUT0 || d4.z >= OUT0 || d4.w >= OUT0) {
            int4   s4 = __ldg(&s4p[q]);
            float4 w4 = __ldg(&w4p[q]);
            int   dd[4] = {d4.x, d4.y, d4.z, d4.w};
            int   ss[4] = {s4.x, s4.y, s4.z, s4.w};
            float ww[4] = {w4.x, w4.y, w4.z, w4.w};
#pragma unroll
            for (int m = 0; m < 4; m++) {
                if (dd[m] >= OUT0) {
                    int o   = dd[m] - OUT0;
                    int j   = ss[m] - ASS0;
                    int pos = atomicAdd(&g_c2[o * CSTR], 1);
                    g_b2[o * CAP2 + pos] =
                        make_float2(__int_as_float(j), ww[m]);
                }
            }
        }
    }
    for (int e = (E4 << 2) + i; e < E_ass; e += nt) {  // tail (E_ass % 4)
        int d = a_dst[e];
        if (d >= OUT0) {
            int   o = d - OUT0;
            int   j = a_src[e] - ASS0;
            float w = a_w[e];
            int pos = atomicAdd(&g_c2[o * CSTR], 1);
            g_b2[o * CAP2 + pos] = make_float2(__int_as_float(j), w);
        }
    }
}

// ---------------------------------------------------------------- k2: fuse
// Block o: stage edges + counts in parallel, warp-per-edge fold into SMEM
// Mrow (2-edge interleave), then GEMM the row against xT.
__global__ void __launch_bounds__(512) k_fuse(float* __restrict__ out) {
    __shared__ float  sM[IN_F];              // M[o][*]
    __shared__ float2 se[CAP2];              // o's staged edges {j, w2}
    __shared__ int    sn1[CAP2];             // n1 per staged edge
    __shared__ float  part[3][B];
    __shared__ int    sc, slast;
    const int o    = blockIdx.x;
    const int tid  = threadIdx.x;
    const int warp = tid >> 5, lane = tid & 31;

    for (int s = tid; s < IN_F; s += 512) sM[s] = 0.f;
    if (tid == 0) { sc = g_c2[o * CSTR]; g_c2[o * CSTR] = 0; }  // sole reader
    __syncthreads();
    const int n2 = sc;                                 // <= ~252 < 512

    // ---- stage: all edge records, then all n1 counts (2 parallel rounds) ----
    if (tid < n2) se[tid] = __ldg(&g_b2[o * CAP2 + tid]);
    __syncthreads();
    if (tid < n2) sn1[tid] = __ldg(&g_c1[__float_as_int(se[tid].x) * CSTR]);
    __syncthreads();

    // ---- cross: warp per edge, 2 edges interleaved per iteration ----
    for (int t = warp; t < n2; t += 32) {
        int t2 = t + 16;
        bool h2 = (t2 < n2);
        float2 eA = se[t];
        float2 eB = h2 ? se[t2] : make_float2(0.f, 0.f);
        int  nA = sn1[t],            nB = h2 ? sn1[t2] : 0;
        const float2* rA = &g_b1[__float_as_int(eA.x) * CAP1];
        const float2* rB = &g_b1[__float_as_int(eB.x) * CAP1];
        float2 pA = (lane < nA) ? __ldg(&rA[lane]) : make_float2(0.f, 0.f);
        float2 pB = (lane < nB) ? __ldg(&rB[lane]) : make_float2(0.f, 0.f);
        if (lane < nA) atomicAdd(&sM[__float_as_int(pA.x)], pA.y * eA.y);
        if (lane < nB) atomicAdd(&sM[__float_as_int(pB.x)], pB.y * eB.y);
    }
    __syncthreads();

    // ---- gemm: out[b][o] = sum_s sM[s] * xT[s][b] ----
    int g = tid >> 7, b = tid & 127;
    float r = 0.f;
    int s0 = g * 64;
#pragma unroll
    for (int sr = 0; sr < 64; sr += 8) {               // 8 independent loads
        float v[8];
#pragma unroll
        for (int k = 0; k < 8; k++)
            v[k] = g_xT[(s0 + sr + k) * B + b];
#pragma unroll
        for (int k = 0; k < 8; k++)
            r += sM[s0 + sr + k] * v[k];
    }
    if (g > 0) part[g - 1][b] = r;
    __syncthreads();
    if (g == 0)
        out[b * OUT_F + o] = r + part[0][b] + part[1][b] + part[2][b];

    // ---- last block out resets g_c1 (all blocks done reading it) ----
    __syncthreads();
    if (tid == 0) slast = (atomicAdd(&g_done, 1) == OUT_F - 1) ? 1 : 0;
    __syncthreads();
    if (slast) {
        for (int j = tid; j < N_ASS; j += 512) g_c1[j * CSTR] = 0;
        if (tid == 0) g_done = 0;                      // restore for replay
    }
}

// ---------------------------------------------------------------- launch
extern "C" void kernel_launch(void* const* d_in, const int* in_sizes, int n_in,
                              void* d_out, int out_size) {
    const float* x      = (const float*)d_in[0];
    const float* in_w   = (const float*)d_in[1];
    const float* a_w    = (const float*)d_in[2];
    const int*   in_src = (const int*)d_in[3];
    const int*   in_dst = (const int*)d_in[4];
    const int*   a_src  = (const int*)d_in[5];
    const int*   a_dst  = (const int*)d_in[6];
    int E_in  = in_sizes[1];
    int E_ass = in_sizes[2];
    float* out = (float*)d_out;

    k_build<<<1184, 256>>>(x, in_src, in_dst, in_w, E_in,
                           a_src, a_dst, a_w, E_ass);
    k_fuse <<<OUT_F, 512>>>(out);
}

// round 14
// speedup vs baseline: 1.1089x; 1.0982x over previous
#include <cuda_runtime.h>

// Random_RNN two-hop — algebraic collapse: out = (W2*W1) * x^T.
// CONFIRMED BEST STRUCTURE (R11, 19.0us): 3 kernels — build buckets (one
// scan), j-keyed fold into dense M (spread global RED atomics), tiny GEMM.
// Fused variants lost twice (R12/R13). This round: component tweaks only.
//   build: ILP-2 int4 scan @592 blocks; vectorized hop1 edge pass.
//   fold:  out-edge list held in registers, broadcast via shfl (no serial
//          memory loop); memory fallback only if n2 > 32 (ultra-rare).
//   gemm:  unchanged.
// Invariants: line-padded counters (L2 atomics serialize per 128B line),
// counters consumed-and-reset in fold, M zeroed in build -> replay-identical.

#define B      128
#define IN_F   256
#define N_ASS  4096
#define OUT_F  256
#define ASS0   256
#define OUT0   (IN_F + N_ASS)   // 4352
#define CAP1   40               // per-j in-degree  (E 12.8, sd 3.5)
#define CAP2   40               // per-j out-degree to outputs (E 12.8, sd 3.5)
#define XT_N   (IN_F * B)       // 32768
#define MSZ    (OUT_F * IN_F)   // 65536
#define CSTR   32               // counter stride: 32 ints = 128B = 1 L2 line

__device__ float2 g_b1[N_ASS * CAP1];   // in-edges of j:  {s (int bits), w1}
__device__ float2 g_b2[N_ASS * CAP2];   // out-edges of j: {o (int bits), w2}
__device__ int    g_c1[N_ASS * CSTR];   // one counter per L2 line
__device__ int    g_c2[N_ASS * CSTR];
__device__ float  g_xT[IN_F * B];       // x transposed [s][b]
__device__ float  g_M[MSZ];             // dense W2*W1, [o][s]

// ---------------------------------------------------------------- k1: build
__global__ void __launch_bounds__(256, 8)
k_build(const float* __restrict__ x,
        const int* __restrict__ in_src, const int* __restrict__ in_dst,
        const float* __restrict__ in_w, int E_in,
        const int* __restrict__ a_src, const int* __restrict__ a_dst,
        const float* __restrict__ a_w, int E_ass) {
    const int i  = blockIdx.x * 256 + threadIdx.x;
    const int nt = gridDim.x * 256;

    for (int m = i; m < MSZ; m += nt) g_M[m] = 0.f;    // zero M each launch

    // x [B][IN_F] -> xT [IN_F][B]
    for (int idx = i; idx < XT_N; idx += nt) {
        int b = idx >> 8, s = idx & 255;               // IN_F == 256
        g_xT[s * B + b] = x[idx];
    }

    // hop1 edges (~52K): vectorized, bucket by dst assoc j
    {
        const int   F4  = E_in >> 2;
        const int4* d4p = (const int4*)in_dst;
        const int4* s4p = (const int4*)in_src;
        const float4* w4p = (const float4*)in_w;
        for (int q = i; q < F4; q += nt) {
            int4   d4 = __ldg(&d4p[q]);
            int4   s4 = __ldg(&s4p[q]);
            float4 w4 = __ldg(&w4p[q]);
            int   dd[4] = {d4.x, d4.y, d4.z, d4.w};
            int   ss[4] = {s4.x, s4.y, s4.z, s4.w};
            float ww[4] = {w4.x, w4.y, w4.z, w4.w};
#pragma unroll
            for (int m = 0; m < 4; m++) {
                int j   = dd[m] - ASS0;
                int pos = atomicAdd(&g_c1[j * CSTR], 1);
                g_b1[j * CAP1 + pos] = make_float2(__int_as_float(ss[m]), ww[m]);
            }
        }
        for (int e = (F4 << 2) + i; e < E_in; e += nt) {
            int   j = in_dst[e] - ASS0;
            int pos = atomicAdd(&g_c1[j * CSTR], 1);
            g_b1[j * CAP1 + pos] = make_float2(__int_as_float(in_src[e]), in_w[e]);
        }
    }

    // hop2 edges (~891K): ILP-2 int4 dst scan, filter dst >= OUT0, key by SRC j
    {
        const int     E4  = E_ass >> 2;
        const int4*   a4  = (const int4*)a_dst;
        const int4*   s4p = (const int4*)a_src;
        const float4* w4p = (const float4*)a_w;
        for (int q = i; q < E4; q += 2 * nt) {
            int  qb = q + nt;
            int4 dA = __ldg(&a4[q]);                                  // pair of
            int4 dB = (qb < E4) ? __ldg(&a4[qb]) : make_int4(0,0,0,0); // indep loads
#pragma unroll
            for (int h = 0; h < 2; h++) {
                int4 d4 = h ? dB : dA;
                int  qq = h ? qb : q;
                if (h && qb >= E4) break;
                if (d4.x >= OUT0 || d4.y >= OUT0 || d4.z >= OUT0 || d4.w >= OUT0) {
                    int4   s4 = __ldg(&s4p[qq]);
                    float4 w4 = __ldg(&w4p[qq]);
                    int   dd[4] = {d4.x, d4.y, d4.z, d4.w};
                    int   ss[4] = {s4.x, s4.y, s4.z, s4.w};
                    float ww[4] = {w4.x, w4.y, w4.z, w4.w};
#pragma unroll
                    for (int m = 0; m < 4; m++) {
                        if (dd[m] >= OUT0) {
                            int j   = ss[m] - ASS0;    // key by source assoc
                            int o   = dd[m] - OUT0;
                            int pos = atomicAdd(&g_c2[j * CSTR], 1);
                            g_b2[j * CAP2 + pos] =
                                make_float2(__int_as_float(o), ww[m]);
                        }
                    }
                }
            }
        }
        for (int e = (E4 << 2) + i; e < E_ass; e += nt) {  // tail
            int d = a_dst[e];
            if (d >= OUT0) {
                int   j = a_src[e] - ASS0;
                int   o = d - OUT0;
                float w = a_w[e];
                int pos = atomicAdd(&g_c2[j * CSTR], 1);
                g_b2[j * CAP2 + pos] = make_float2(__int_as_float(o), w);
            }
        }
    }
}

// ---------------------------------------------------------------- k2: fold
// One warp per assoc j. Lane t owns in-edge t (s,w1). Out-edges preloaded
// into lane registers, broadcast by shfl — no memory in the inner loop.
// Consumes + resets both counters (replay determinism).
__global__ void __launch_bounds__(256) k_fold() {
    int warp = threadIdx.x >> 5, lane = threadIdx.x & 31;
    int j = blockIdx.x * 8 + warp;                     // 512 blocks x 8 warps
    int n1 = __ldg(&g_c1[j * CSTR]);
    int n2 = __ldg(&g_c2[j * CSTR]);
    if (lane == 0) { g_c1[j * CSTR] = 0; g_c2[j * CSTR] = 0; }
    const float2* e1 = &g_b1[j * CAP1];
    const float2* e2 = &g_b2[j * CAP2];

    // lane-resident out-edge (first 32), and lane-resident in-edge (first 32)
    float2 my2 = (lane < n2) ? __ldg(&e2[lane]) : make_float2(0.f, 0.f);
    float2 my1 = (lane < n1) ? __ldg(&e1[lane]) : make_float2(0.f, 0.f);

    int   s  = __float_as_int(my1.x);
    float w1 = my1.y;
    int nb = (n2 < 32) ? n2 : 32;
    for (int k = 0; k < nb; k++) {                     // register broadcast
        int   o  = __shfl_sync(0xffffffffu, __float_as_int(my2.x), k);
        float w2 = __shfl_sync(0xffffffffu, my2.y, k);
        if (lane < n1)
            atomicAdd(&g_M[o * IN_F + s], w1 * w2);    // RED, spread addrs
    }
    for (int k = 32; k < n2; k++) {                    // ultra-rare overflow
        float2 p2 = __ldg(&e2[k]);
        if (lane < n1)
            atomicAdd(&g_M[__float_as_int(p2.x) * IN_F + s], w1 * p2.y);
    }
    // in-edges beyond lane 32 (n1 > 32 impossible at CAP ~26 max, but safe):
    for (int t = lane + 32; t < n1; t += 32) {
        float2 p1 = __ldg(&e1[t]);
        int   s2  = __float_as_int(p1.x);
        for (int k = 0; k < n2; k++) {
            float2 p2 = __ldg(&e2[k]);
            atomicAdd(&g_M[__float_as_int(p2.x) * IN_F + s2], p1.y * p2.y);
        }
    }
}

// ---------------------------------------------------------------- k3: gemm
// out[b][o] = sum_s M[o][s] * xT[s][b]; block o; 4 s-groups x 128 b-threads.
__global__ void __launch_bounds__(512) k_gemm(float* __restrict__ out) {
    __shared__ float sM[IN_F];
    __shared__ float part[3][B];
    int o = blockIdx.x;
    int g = threadIdx.x >> 7, b = threadIdx.x & 127;
    for (int s = threadIdx.x; s < IN_F; s += 512) sM[s] = g_M[o * IN_F + s];
    __syncthreads();
    float r = 0.f;
    int s0 = g * 64;
#pragma unroll
    for (int sr = 0; sr < 64; sr += 8) {               // 8 independent loads
        float v[8];
#pragma unroll
        for (int k = 0; k < 8; k++)
            v[k] = g_xT[(s0 + sr + k) * B + b];
#pragma unroll
        for (int k = 0; k < 8; k++)
            r += sM[s0 + sr + k] * v[k];
    }
    if (g > 0) part[g - 1][b] = r;
    __syncthreads();
    if (g == 0)
        out[b * OUT_F + o] = r + part[0][b] + part[1][b] + part[2][b];
}

// ---------------------------------------------------------------- launch
extern "C" void kernel_launch(void* const* d_in, const int* in_sizes, int n_in,
                              void* d_out, int out_size) {
    const float* x      = (const float*)d_in[0];
    const float* in_w   = (const float*)d_in[1];
    const float* a_w    = (const float*)d_in[2];
    const int*   in_src = (const int*)d_in[3];
    const int*   in_dst = (const int*)d_in[4];
    const int*   a_src  = (const int*)d_in[5];
    const int*   a_dst  = (const int*)d_in[6];
    int E_in  = in_sizes[1];
    int E_ass = in_sizes[2];
    float* out = (float*)d_out;

    k_build<<<592, 256>>>(x, in_src, in_dst, in_w, E_in,
                          a_src, a_dst, a_w, E_ass);
    k_fold <<<N_ASS / 8, 256>>>();
    k_gemm <<<OUT_F, 512>>>(out);
}

// round 15
// speedup vs baseline: 1.1550x; 1.0415x over previous
#include <cuda_runtime.h>

// Random_RNN two-hop — algebraic collapse: out = (W2*W1) * x^T.
// Best-measured components, recombined:
//   build: R11 scan shape EXACTLY (1184x256 flat grid-stride int4 scan —
//          R14 proved occupancy > per-thread ILP here) + vectorized hop1 pass.
//   fold:  j-keyed warp fold, out-edges broadcast via shfl (register inner
//          loop, spread RED atomics into dense M).
//   gemm:  256x256 M row in smem x 128-batch xT, 4-way split, smem reduce.
// Invariants: line-padded counters (L2 atomics serialize per 128B line),
// counters consumed-and-reset in fold, M zeroed in build -> replay-identical.

#define B      128
#define IN_F   256
#define N_ASS  4096
#define OUT_F  256
#define ASS0   256
#define OUT0   (IN_F + N_ASS)   // 4352
#define CAP1   40               // per-j in-degree  (E 12.8, sd 3.5)
#define CAP2   40               // per-j out-degree to outputs (E 12.8, sd 3.5)
#define XT_N   (IN_F * B)       // 32768
#define MSZ    (OUT_F * IN_F)   // 65536
#define CSTR   32               // counter stride: 32 ints = 128B = 1 L2 line

__device__ float2 g_b1[N_ASS * CAP1];   // in-edges of j:  {s (int bits), w1}
__device__ float2 g_b2[N_ASS * CAP2];   // out-edges of j: {o (int bits), w2}
__device__ int    g_c1[N_ASS * CSTR];   // one counter per L2 line
__device__ int    g_c2[N_ASS * CSTR];
__device__ float  g_xT[IN_F * B];       // x transposed [s][b]
__device__ float  g_M[MSZ];             // dense W2*W1, [o][s]

// ---------------------------------------------------------------- k1: build
// 1184 blocks x 256, flat grid-stride (pinned: best scan shape, R10/R11/R14).
__global__ void __launch_bounds__(256, 8)
k_build(const float* __restrict__ x,
        const int* __restrict__ in_src, const int* __restrict__ in_dst,
        const float* __restrict__ in_w, int E_in,
        const int* __restrict__ a_src, const int* __restrict__ a_dst,
        const float* __restrict__ a_w, int E_ass) {
    const int i  = blockIdx.x * 256 + threadIdx.x;
    const int nt = gridDim.x * 256;                    // 303104

    if (i < MSZ) g_M[i] = 0.f;                         // nt > MSZ: one shot

    // x [B][IN_F] -> xT [IN_F][B]
    for (int idx = i; idx < XT_N; idx += nt) {
        int b = idx >> 8, s = idx & 255;               // IN_F == 256
        g_xT[s * B + b] = x[idx];
    }

    // hop1 edges (~52K): vectorized, bucket by dst assoc j
    {
        const int     F4  = E_in >> 2;
        const int4*   d4p = (const int4*)in_dst;
        const int4*   s4p = (const int4*)in_src;
        const float4* w4p = (const float4*)in_w;
        for (int q = i; q < F4; q += nt) {
            int4   d4 = __ldg(&d4p[q]);
            int4   s4 = __ldg(&s4p[q]);
            float4 w4 = __ldg(&w4p[q]);
            int   dd[4] = {d4.x, d4.y, d4.z, d4.w};
            int   ss[4] = {s4.x, s4.y, s4.z, s4.w};
            float ww[4] = {w4.x, w4.y, w4.z, w4.w};
#pragma unroll
            for (int m = 0; m < 4; m++) {
                int j   = dd[m] - ASS0;
                int pos = atomicAdd(&g_c1[j * CSTR], 1);
                g_b1[j * CAP1 + pos] = make_float2(__int_as_float(ss[m]), ww[m]);
            }
        }
        for (int e = (F4 << 2) + i; e < E_in; e += nt) {
            int   j = in_dst[e] - ASS0;
            int pos = atomicAdd(&g_c1[j * CSTR], 1);
            g_b1[j * CAP1 + pos] = make_float2(__int_as_float(in_src[e]), in_w[e]);
        }
    }

    // hop2 edges (~891K): flat int4 dst scan, filter dst >= OUT0, key by SRC j
    {
        const int     E4  = E_ass >> 2;
        const int4*   a4  = (const int4*)a_dst;
        const int4*   s4p = (const int4*)a_src;
        const float4* w4p = (const float4*)a_w;
        for (int q = i; q < E4; q += nt) {
            int4 d4 = __ldg(&a4[q]);
            if (d4.x >= OUT0 || d4.y >= OUT0 || d4.z >= OUT0 || d4.w >= OUT0) {
                int4   s4 = __ldg(&s4p[q]);            // conditional side loads
                float4 w4 = __ldg(&w4p[q]);
                int   dd[4] = {d4.x, d4.y, d4.z, d4.w};
                int   ss[4] = {s4.x, s4.y, s4.z, s4.w};
                float ww[4] = {w4.x, w4.y, w4.z, w4.w};
#pragma unroll
                for (int m = 0; m < 4; m++) {
                    if (dd[m] >= OUT0) {
                        int j   = ss[m] - ASS0;        // key by source assoc
                        int o   = dd[m] - OUT0;
                        int pos = atomicAdd(&g_c2[j * CSTR], 1);
                        g_b2[j * CAP2 + pos] =
                            make_float2(__int_as_float(o), ww[m]);
                    }
                }
            }
        }
        for (int e = (E4 << 2) + i; e < E_ass; e += nt) {  // tail (E_ass % 4)
            int d = a_dst[e];
            if (d >= OUT0) {
                int   j = a_src[e] - ASS0;
                int   o = d - OUT0;
                float w = a_w[e];
                int pos = atomicAdd(&g_c2[j * CSTR], 1);
                g_b2[j * CAP2 + pos] = make_float2(__int_as_float(o), w);
            }
        }
    }
}

// ---------------------------------------------------------------- k2: fold
// One warp per assoc j. Lane t owns in-edge t (s,w1); out-edges lane-resident,
// broadcast via shfl — register-only inner loop, spread RED atomics into M.
// Consumes + resets both counters (replay determinism).
__global__ void __launch_bounds__(256) k_fold() {
    int warp = threadIdx.x >> 5, lane = threadIdx.x & 31;
    int j = blockIdx.x * 8 + warp;                     // 512 blocks x 8 warps
    int n1 = __ldg(&g_c1[j * CSTR]);
    int n2 = __ldg(&g_c2[j * CSTR]);
    if (lane == 0) { g_c1[j * CSTR] = 0; g_c2[j * CSTR] = 0; }
    const float2* e1 = &g_b1[j * CAP1];
    const float2* e2 = &g_b2[j * CAP2];

    float2 my2 = (lane < n2) ? __ldg(&e2[lane]) : make_float2(0.f, 0.f);
    float2 my1 = (lane < n1) ? __ldg(&e1[lane]) : make_float2(0.f, 0.f);

    int   s  = __float_as_int(my1.x);
    float w1 = my1.y;
    int nb = (n2 < 32) ? n2 : 32;
    for (int k = 0; k < nb; k++) {                     // register broadcast
        int   o  = __shfl_sync(0xffffffffu, __float_as_int(my2.x), k);
        float w2 = __shfl_sync(0xffffffffu, my2.y, k);
        if (lane < n1)
            atomicAdd(&g_M[o * IN_F + s], w1 * w2);    // RED, spread addrs
    }
    for (int k = 32; k < n2; k++) {                    // ultra-rare overflow
        float2 p2 = __ldg(&e2[k]);
        if (lane < n1)
            atomicAdd(&g_M[__float_as_int(p2.x) * IN_F + s], w1 * p2.y);
    }
    for (int t = lane + 32; t < n1; t += 32) {         // n1>32 impossible; safe
        float2 p1 = __ldg(&e1[t]);
        int   s2  = __float_as_int(p1.x);
        for (int k = 0; k < n2; k++) {
            float2 p2 = __ldg(&e2[k]);
            atomicAdd(&g_M[__float_as_int(p2.x) * IN_F + s2], p1.y * p2.y);
        }
    }
}

// ---------------------------------------------------------------- k3: gemm
// out[b][o] = sum_s M[o][s] * xT[s][b]; block o; 4 s-groups x 128 b-threads.
__global__ void __launch_bounds__(512) k_gemm(float* __restrict__ out) {
    __shared__ float sM[IN_F];
    __shared__ float part[3][B];
    int o = blockIdx.x;
    int g = threadIdx.x >> 7, b = threadIdx.x & 127;
    for (int s = threadIdx.x; s < IN_F; s += 512) sM[s] = g_M[o * IN_F + s];
    __syncthreads();
    float r = 0.f;
    int s0 = g * 64;
#pragma unroll
    for (int sr = 0; sr < 64; sr += 8) {               // 8 independent loads
        float v[8];
#pragma unroll
        for (int k = 0; k < 8; k++)
            v[k] = g_xT[(s0 + sr + k) * B + b];
#pragma unroll
        for (int k = 0; k < 8; k++)
            r += sM[s0 + sr + k] * v[k];
    }
    if (g > 0) part[g - 1][b] = r;
    __syncthreads();
    if (g == 0)
        out[b * OUT_F + o] = r + part[0][b] + part[1][b] + part[2][b];
}

// ---------------------------------------------------------------- launch
extern "C" void kernel_launch(void* const* d_in, const int* in_sizes, int n_in,
                              void* d_out, int out_size) {
    const float* x      = (const float*)d_in[0];
    const float* in_w   = (const float*)d_in[1];
    const float* a_w    = (const float*)d_in[2];
    const int*   in_src = (const int*)d_in[3];
    const int*   in_dst = (const int*)d_in[4];
    const int*   a_src  = (const int*)d_in[5];
    const int*   a_dst  = (const int*)d_in[6];
    int E_in  = in_sizes[1];
    int E_ass = in_sizes[2];
    float* out = (float*)d_out;

    k_build<<<1184, 256>>>(x, in_src, in_dst, in_w, E_in,
                           a_src, a_dst, a_w, E_ass);
    k_fold <<<N_ASS / 8, 256>>>();
    k_gemm <<<OUT_F, 512>>>(out);
}